// round 15
// baseline (speedup 1.0000x reference)
#include <cuda_runtime.h>
#include <cuda_fp16.h>
#include <cstdint>

// ----------------------------------------------------------------------------
// EBTBlock (DiT adaLN-Zero): B=8, S=1024, D=1024, H=16, DH=64, fp32.
// Round 15: convw+mods merged into one launch (block-range dispatch, co-run);
// 1/8 attention scale folded into qkv EPI-3 Q write (power-of-2, exact);
// flash softmax drops the scale multiplies. Cores otherwise = R14 (929.8us).
// ----------------------------------------------------------------------------

#define B_    8
#define S_    1024
#define D_    1024
#define H_    16
#define DH_   64
#define M_    (B_ * S_)
#define SIXD_ (6 * D_)

// Scratch
__device__ float  g_mods[B_ * SIXD_];
__device__ __align__(16) __half g_xm[M_ * D_];
__device__ __align__(16) __half g_qkv[M_ * 3 * D_];
__device__ __align__(16) __half g_vt[B_ * H_ * DH_ * S_];
__device__ __align__(16) __half g_o[M_ * D_];
__device__ __align__(16) __half g_h[M_ * 4 * D_];
__device__ __align__(16) __half g_w[12 * 1024 * 1024];

// ===========================================================================
// helpers
// ===========================================================================
__device__ __forceinline__ uint32_t smem_u32(const void* p) {
    uint32_t a;
    asm("{ .reg .u64 t; cvta.to.shared.u64 t, %1; cvt.u32.u64 %0, t; }"
        : "=r"(a) : "l"(p));
    return a;
}
__device__ __forceinline__ void cpasync16(uint32_t dst, const void* src) {
    asm volatile("cp.async.ca.shared.global [%0], [%1], 16;"
                 :: "r"(dst), "l"(src) : "memory");
}
__device__ __forceinline__ void mma_f16(float* d, const uint32_t* a,
                                        const uint32_t* b) {
    asm volatile(
        "mma.sync.aligned.m16n8k16.row.col.f32.f16.f16.f32 "
        "{%0,%1,%2,%3}, {%4,%5,%6,%7}, {%8,%9}, {%0,%1,%2,%3};"
        : "+f"(d[0]), "+f"(d[1]), "+f"(d[2]), "+f"(d[3])
        : "r"(a[0]), "r"(a[1]), "r"(a[2]), "r"(a[3]), "r"(b[0]), "r"(b[1]));
}
__device__ __forceinline__ uint32_t packh2(float x, float y) {
    __half2 h = __floats2half2_rn(x, y);
    return *(uint32_t*)&h;
}
__device__ __forceinline__ float gelu_tanh(float x) {
    float x3 = x * x * x;
    float t = tanhf(0.7978845608028654f * (x + 0.044715f * x3));
    return 0.5f * x * (1.0f + t);
}

// ===========================================================================
// dense fp16 GEMM (NT): CTA 128x256, 8 warps (2x4), warp 64x64, k-chunk 64,
// 3-stage cp.async — at the mma.sync wall (R12/R14 core).
// EPI 0: half out  EPI 1: half gelu(v+bias)  EPI 2: fp32 resid+gate*(v+bias)
// EPI 3: qkv writer (Q scaled by 0.125 exact; K normal; V transposed)
// ===========================================================================
#define DSTRH 72
#define ASTGH (128 * DSTRH)
#define BSTGH (256 * DSTRH)
#define STGH  (ASTGH + BSTGH)
#define GM_SMEM (3 * STGH * 2)        // 165888 B

template <int EPI>
__global__ __launch_bounds__(256, 1)
void gemm_h(const __half* __restrict__ A, int lda,
            const __half* __restrict__ Bw, int ldb,
            void* __restrict__ Cv, int ldc,
            int K, const float* __restrict__ bias,
            const float* __restrict__ resid,
            const float* __restrict__ gate,
            __half* __restrict__ vt) {
    extern __shared__ __half smh[];
    const int tid = threadIdx.x, lane = tid & 31, wid = tid >> 5;
    const int wm = wid & 1, wn = wid >> 1;
    const int m0 = blockIdx.y * 128, n0 = blockIdx.x * 256;
    const uint32_t sbase = smem_u32(smh);
    const int q = lane & 3, lh = lane >> 2;

    float acc[4][8][4];
#pragma unroll
    for (int i = 0; i < 4; i++)
#pragma unroll
        for (int j = 0; j < 8; j++)
#pragma unroll
            for (int e = 0; e < 4; e++) acc[i][j][e] = 0.0f;

    const int nch = K >> 6;

    auto load_stage = [&](int s, int k0) {
#pragma unroll
        for (int it = 0; it < 4; it++) {
            int idx = tid + it * 256;
            int r = idx >> 3, c8 = (idx & 7) << 3;
            cpasync16(sbase + (uint32_t)(s * STGH + r * DSTRH + c8) * 2,
                      A + (size_t)(m0 + r) * lda + k0 + c8);
        }
#pragma unroll
        for (int it = 0; it < 8; it++) {
            int idx = tid + it * 256;
            int r = idx >> 3, c8 = (idx & 7) << 3;
            cpasync16(sbase + (uint32_t)(s * STGH + ASTGH + r * DSTRH + c8) * 2,
                      Bw + (size_t)(n0 + r) * ldb + k0 + c8);
        }
    };

    load_stage(0, 0);
    asm volatile("cp.async.commit_group;" ::: "memory");
    if (nch > 1) load_stage(1, 64);
    asm volatile("cp.async.commit_group;" ::: "memory");

    int stg = 0;
    for (int i = 0; i < nch; i++) {
        asm volatile("cp.async.wait_group 1;" ::: "memory");
        __syncthreads();
        if (i + 2 < nch) {
            int s2 = stg + 2; if (s2 >= 3) s2 -= 3;
            load_stage(s2, (i + 2) << 6);
        }
        asm volatile("cp.async.commit_group;" ::: "memory");

        const uint32_t* sAw = (const uint32_t*)(smh + stg * STGH);
        const uint32_t* sBw = sAw + ASTGH / 2;
#pragma unroll
        for (int kk = 0; kk < 4; kk++) {
            const int kw = kk * 8;
            uint32_t a[4][4];
#pragma unroll
            for (int ii = 0; ii < 4; ii++) {
                int rw = (wm * 64 + ii * 16 + lh) * (DSTRH / 2) + kw;
                a[ii][0] = sAw[rw + q];
                a[ii][1] = sAw[rw + 8 * (DSTRH / 2) + q];
                a[ii][2] = sAw[rw + q + 4];
                a[ii][3] = sAw[rw + 8 * (DSTRH / 2) + q + 4];
            }
#pragma unroll
            for (int j = 0; j < 8; j++) {
                int nw = (wn * 64 + j * 8 + lh) * (DSTRH / 2) + kw;
                uint32_t b[2];
                b[0] = sBw[nw + q];
                b[1] = sBw[nw + q + 4];
#pragma unroll
                for (int ii = 0; ii < 4; ii++)
                    mma_f16(acc[ii][j], a[ii], b);
            }
        }
        if (++stg == 3) stg = 0;
    }

#pragma unroll
    for (int ii = 0; ii < 4; ii++) {
        int gm0 = m0 + wm * 64 + ii * 16 + lh;
#pragma unroll
        for (int j = 0; j < 8; j++) {
            int gn = n0 + wn * 64 + j * 8 + 2 * q;
#pragma unroll
            for (int h = 0; h < 2; h++) {
                int gm = gm0 + h * 8;
                float v0 = acc[ii][j][h * 2], v1 = acc[ii][j][h * 2 + 1];
                if (EPI == 0) {
                    *(__half2*)((__half*)Cv + (size_t)gm * ldc + gn) =
                        __floats2half2_rn(v0, v1);
                } else if (EPI == 1) {
                    v0 = gelu_tanh(v0 + bias[gn]);
                    v1 = gelu_tanh(v1 + bias[gn + 1]);
                    *(__half2*)((__half*)Cv + (size_t)gm * ldc + gn) =
                        __floats2half2_rn(v0, v1);
                } else if (EPI == 2) {
                    float* C = (float*)Cv;
                    float2 o;
                    o.x = resid[(size_t)gm * ldc + gn] +
                          gate[(size_t)(gm >> 10) * SIXD_ + gn] * (v0 + bias[gn]);
                    o.y = resid[(size_t)gm * ldc + gn + 1] +
                          gate[(size_t)(gm >> 10) * SIXD_ + gn + 1] * (v1 + bias[gn + 1]);
                    *(float2*)(C + (size_t)gm * ldc + gn) = o;
                } else {            // EPI 3: qkv writer
                    if (gn < D_) {               // Q: pre-scale by 1/8 (exact)
                        *(__half2*)((__half*)Cv + (size_t)gm * ldc + gn) =
                            __floats2half2_rn(v0 * 0.125f, v1 * 0.125f);
                    } else if (gn < 2 * D_) {    // K
                        *(__half2*)((__half*)Cv + (size_t)gm * ldc + gn) =
                            __floats2half2_rn(v0, v1);
                    } else {                     // V -> transposed
                        int hh = (gn - 2 * D_) >> 6, dh = (gn - 2 * D_) & 63;
                        int bb = gm >> 10, s = gm & 1023;
                        size_t rb = ((size_t)(bb * H_ + hh) * DH_ + dh) * S_ + s;
                        vt[rb]      = __float2half_rn(v0);
                        vt[rb + S_] = __float2half_rn(v1);
                    }
                }
            }
        }
    }
}

// ===========================================================================
// Fused flash attention, fp16 mma, q-tile 256, K/V double-buffered,
// P in registers (C-frag == A-frag identity). Q arrives pre-scaled.
// grid (S/256, B*H), 512 thr. SMEM = 108544 B.
// ===========================================================================
#define QSH 72
#define VTH 136
#define KSTG (128 * QSH)
#define VSTG (64 * VTH)
#define FA_SMEM ((256 * QSH + 2 * KSTG + 2 * VSTG) * 2)

__global__ __launch_bounds__(512, 1)
void flash_kernel(const __half* __restrict__ qkv,
                  const __half* __restrict__ vt,
                  __half* __restrict__ O) {
    extern __shared__ __half fsh[];
    __half* Qs = fsh;
    __half* Ks = Qs + 256 * QSH;
    __half* Vs = Ks + 2 * KSTG;
    const uint32_t sbQ = smem_u32(Qs), sbK = smem_u32(Ks), sbV = smem_u32(Vs);
    const uint32_t* Qw = (const uint32_t*)Qs;

    const int tid = threadIdx.x, lane = tid & 31, wid = tid >> 5;
    const int q = lane & 3, lh = lane >> 2;
    const int w16 = wid * 16;
    const int bh = blockIdx.y, bb = bh >> 4, hh = bh & 15;
    const int q0 = blockIdx.x * 256;
    const size_t base = (size_t)bb * S_ * 3 * D_ + (size_t)hh * DH_;
    const size_t vbase = (size_t)bh * DH_ * S_;

    auto load_kv = [&](int s, int kv0) {
        const uint32_t kb = sbK + (uint32_t)(s * KSTG) * 2;
        const uint32_t vb = sbV + (uint32_t)(s * VSTG) * 2;
#pragma unroll
        for (int it = 0; it < 2; it++) {
            int idx = tid + it * 512;
            int r = idx >> 3, c8 = (idx & 7) << 3;
            cpasync16(kb + (uint32_t)(r * QSH + c8) * 2,
                      qkv + base + D_ + (size_t)(kv0 + r) * 3 * D_ + c8);
        }
#pragma unroll
        for (int it = 0; it < 2; it++) {
            int idx = tid + it * 512;
            int r = idx >> 4, c8 = (idx & 15) << 3;
            cpasync16(vb + (uint32_t)(r * VTH + c8) * 2,
                      vt + vbase + (size_t)r * S_ + kv0 + c8);
        }
    };

#pragma unroll
    for (int it = 0; it < 4; it++) {
        int idx = tid + it * 512;
        int r = idx >> 3, c8 = (idx & 7) << 3;
        cpasync16(sbQ + (uint32_t)(r * QSH + c8) * 2,
                  qkv + base + (size_t)(q0 + r) * 3 * D_ + c8);
    }
    load_kv(0, 0);
    asm volatile("cp.async.commit_group;" ::: "memory");

    float accO[8][4];
#pragma unroll
    for (int j = 0; j < 8; j++)
#pragma unroll
        for (int e = 0; e < 4; e++) accO[j][e] = 0.0f;
    float mstate[2] = {-1e30f, -1e30f};
    float lstate[2] = {0.0f, 0.0f};

    for (int t = 0; t < 8; t++) {
        if (t + 1 < 8) {
            load_kv((t + 1) & 1, (t + 1) * 128);
            asm volatile("cp.async.commit_group;" ::: "memory");
            asm volatile("cp.async.wait_group 1;" ::: "memory");
        } else {
            asm volatile("cp.async.wait_group 0;" ::: "memory");
        }
        __syncthreads();

        const uint32_t* Kw = (const uint32_t*)(Ks + (t & 1) * KSTG);
        const uint32_t* Vw = (const uint32_t*)(Vs + (t & 1) * VSTG);

        // S = Qscaled @ K^T (warp tile 16 x 128)
        float sc[16][4];
#pragma unroll
        for (int j = 0; j < 16; j++)
#pragma unroll
            for (int e = 0; e < 4; e++) sc[j][e] = 0.0f;
#pragma unroll
        for (int kk = 0; kk < 4; kk++) {
            const int kw = kk * 8;
            uint32_t a[4];
            int rw = (w16 + lh) * (QSH / 2) + kw;
            a[0] = Qw[rw + q];
            a[1] = Qw[rw + 8 * (QSH / 2) + q];
            a[2] = Qw[rw + q + 4];
            a[3] = Qw[rw + 8 * (QSH / 2) + q + 4];
#pragma unroll
            for (int j = 0; j < 16; j++) {
                int nw = (j * 8 + lh) * (QSH / 2) + kw;
                uint32_t b[2] = {Kw[nw + q], Kw[nw + q + 4]};
                mma_f16(sc[j], a, b);
            }
        }

        // online softmax per row pair (scores already scaled)
#pragma unroll
        for (int h2 = 0; h2 < 2; h2++) {
            float mx = -1e30f;
#pragma unroll
            for (int j = 0; j < 16; j++)
                mx = fmaxf(mx, fmaxf(sc[j][h2 * 2], sc[j][h2 * 2 + 1]));
            mx = fmaxf(mx, __shfl_xor_sync(0xffffffffu, mx, 1));
            mx = fmaxf(mx, __shfl_xor_sync(0xffffffffu, mx, 2));
            float mn = fmaxf(mstate[h2], mx);
            float f = __expf(mstate[h2] - mn);
            mstate[h2] = mn;
            float rs = 0.0f;
#pragma unroll
            for (int j = 0; j < 16; j++) {
#pragma unroll
                for (int e = 0; e < 2; e++) {
                    float p = __expf(sc[j][h2 * 2 + e] - mn);
                    rs += p;
                    sc[j][h2 * 2 + e] = p;
                }
            }
            rs += __shfl_xor_sync(0xffffffffu, rs, 1);
            rs += __shfl_xor_sync(0xffffffffu, rs, 2);
            lstate[h2] = lstate[h2] * f + rs;
#pragma unroll
            for (int j = 0; j < 8; j++) {
                accO[j][h2 * 2] *= f;
                accO[j][h2 * 2 + 1] *= f;
            }
        }

        // O += P @ V — P direct from C-fragments (layout identity)
#pragma unroll
        for (int kb = 0; kb < 8; kb++) {
            uint32_t a[4];
            a[0] = packh2(sc[2 * kb][0],     sc[2 * kb][1]);
            a[1] = packh2(sc[2 * kb][2],     sc[2 * kb][3]);
            a[2] = packh2(sc[2 * kb + 1][0], sc[2 * kb + 1][1]);
            a[3] = packh2(sc[2 * kb + 1][2], sc[2 * kb + 1][3]);
            const int kw = kb * 8;
#pragma unroll
            for (int j = 0; j < 8; j++) {
                int nw = (j * 8 + lh) * (VTH / 2) + kw;
                uint32_t b[2] = {Vw[nw + q], Vw[nw + q + 4]};
                mma_f16(accO[j], a, b);
            }
        }
        __syncthreads();
    }

    float inv0 = 1.0f / lstate[0], inv1 = 1.0f / lstate[1];
#pragma unroll
    for (int h2 = 0; h2 < 2; h2++) {
        float inv = h2 ? inv1 : inv0;
        size_t row = (size_t)(bb * S_ + q0 + w16 + lh + 8 * h2);
#pragma unroll
        for (int j = 0; j < 8; j++) {
            *(__half2*)(O + row * D_ + hh * DH_ + j * 8 + 2 * q) =
                __floats2half2_rn(accO[j][h2 * 2] * inv,
                                  accO[j][h2 * 2 + 1] * inv);
        }
    }
}

// ===========================================================================
// small kernels
// ===========================================================================
__device__ __forceinline__ float blk_reduce_sum(float v, float* red) {
    int lane = threadIdx.x & 31, w = threadIdx.x >> 5;
#pragma unroll
    for (int o = 16; o; o >>= 1) v += __shfl_xor_sync(0xffffffffu, v, o);
    if (lane == 0) red[w] = v;
    __syncthreads();
    if (w == 0) {
        v = (lane < 8) ? red[lane] : 0.0f;
#pragma unroll
        for (int o = 4; o; o >>= 1) v += __shfl_xor_sync(0xffffffffu, v, o);
        if (lane == 0) red[0] = v;
    }
    __syncthreads();
    float r = red[0];
    __syncthreads();
    return r;
}

// Merged head kernel: blocks [0, 3072) convert weights (4 float4/thread);
// blocks [3072, 3120) compute adaLN mods (jb = idx%24, g = idx/24).
// Independent workloads co-running in one launch.
__global__ void head_kernel(const float4* __restrict__ s0,
                            const float4* __restrict__ s1,
                            const float4* __restrict__ s2,
                            const float4* __restrict__ s3,
                            __half* __restrict__ dst,
                            const float* __restrict__ y,
                            const float* __restrict__ w,
                            const float* __restrict__ bias,
                            float* __restrict__ mods) {
    __shared__ float sy[4][D_];
    int tid = threadIdx.x;
    if (blockIdx.x < 3072) {
        // --- weight conversion ---
        int basei = blockIdx.x * 1024 + tid;
#pragma unroll
        for (int k = 0; k < 4; k++) {
            int i = basei + k * 256;
            const float4* s;
            int off;
            if (i < 786432)        { s = s0; off = i; }
            else if (i < 1048576)  { s = s1; off = i - 786432; }
            else if (i < 2097152)  { s = s2; off = i - 1048576; }
            else                   { s = s3; off = i - 2097152; }
            float4 v = s[off];
            __half2 h0 = __floats2half2_rn(v.x, v.y);
            __half2 h1 = __floats2half2_rn(v.z, v.w);
            *(uint2*)(dst + 4 * (size_t)i) = make_uint2(
                *(uint32_t*)&h0, *(uint32_t*)&h1);
        }
        return;
    }
    // --- adaLN mods (w read 2x total; identical per-(b,j) summation order) ---
    int idx = blockIdx.x - 3072;
    int jb = idx % 24, g = idx / 24;
#pragma unroll
    for (int b4 = 0; b4 < 4; b4++) {
        float4 yv = ((const float4*)(y + (4 * g + b4) * D_))[tid];
        sy[b4][tid * 4 + 0] = yv.x / (1.0f + expf(-yv.x));
        sy[b4][tid * 4 + 1] = yv.y / (1.0f + expf(-yv.y));
        sy[b4][tid * 4 + 2] = yv.z / (1.0f + expf(-yv.z));
        sy[b4][tid * 4 + 3] = yv.w / (1.0f + expf(-yv.w));
    }
    __syncthreads();
    int j = jb * 256 + tid;
    float acc[4];
#pragma unroll
    for (int b4 = 0; b4 < 4; b4++) acc[b4] = bias[j];
    const float4* w4 = (const float4*)(w + (long)j * D_);
#pragma unroll 4
    for (int k = 0; k < D_ / 4; k++) {
        float4 wv = w4[k];
#pragma unroll
        for (int b4 = 0; b4 < 4; b4++) {
            acc[b4] += sy[b4][4 * k + 0] * wv.x + sy[b4][4 * k + 1] * wv.y +
                       sy[b4][4 * k + 2] * wv.z + sy[b4][4 * k + 3] * wv.w;
        }
    }
#pragma unroll
    for (int b4 = 0; b4 < 4; b4++)
        mods[(4 * g + b4) * SIXD_ + j] = acc[b4];
}

__global__ void ln_mod_kernel(const float* __restrict__ X,
                              const float* __restrict__ mods,
                              int sh_off, int sc_off,
                              __half* __restrict__ out) {
    __shared__ float red[32];
    long row = blockIdx.x;
    int b = (int)(row >> 10);
    int tid = threadIdx.x;
    float4 v = ((const float4*)(X + row * D_))[tid];
    float s = v.x + v.y + v.z + v.w;
    s = blk_reduce_sum(s, red);
    float mean = s * (1.0f / D_);
    float dx = v.x - mean, dy = v.y - mean, dz = v.z - mean, dw = v.w - mean;
    float sq = dx * dx + dy * dy + dz * dz + dw * dw;
    sq = blk_reduce_sum(sq, red);
    float inv = rsqrtf(sq * (1.0f / D_) + 1e-5f);
    const float* mrow = mods + b * SIXD_;
    int c = tid * 4;
    float o0 = dx * inv * (1.0f + mrow[sc_off + c + 0]) + mrow[sh_off + c + 0];
    float o1 = dy * inv * (1.0f + mrow[sc_off + c + 1]) + mrow[sh_off + c + 1];
    float o2 = dz * inv * (1.0f + mrow[sc_off + c + 2]) + mrow[sh_off + c + 2];
    float o3 = dw * inv * (1.0f + mrow[sc_off + c + 3]) + mrow[sh_off + c + 3];
    __half2 h0 = __floats2half2_rn(o0, o1);
    __half2 h1 = __floats2half2_rn(o2, o3);
    *(uint2*)(out + row * (size_t)D_ + c) = make_uint2(
        *(uint32_t*)&h0, *(uint32_t*)&h1);
}

// ===========================================================================
// host launcher
// ===========================================================================
extern "C" void kernel_launch(void* const* d_in, const int* in_sizes, int n_in,
                              void* d_out, int out_size) {
    const float* x       = (const float*)d_in[0];
    const float* y       = (const float*)d_in[1];
    const float* w_adaln = (const float*)d_in[2];
    const float* b_adaln = (const float*)d_in[3];
    const float* w_qkv   = (const float*)d_in[4];
    const float* w_proj  = (const float*)d_in[5];
    const float* b_proj  = (const float*)d_in[6];
    const float* w_fc1   = (const float*)d_in[7];
    const float* b_fc1   = (const float*)d_in[8];
    const float* w_fc2   = (const float*)d_in[9];
    const float* b_fc2   = (const float*)d_in[10];
    float* out = (float*)d_out;

    float *mods_p;
    __half *xm_p, *qkv_p, *vt_p, *o_p, *h_p, *w_p;
    cudaGetSymbolAddress((void**)&mods_p, g_mods);
    cudaGetSymbolAddress((void**)&xm_p,   g_xm);
    cudaGetSymbolAddress((void**)&qkv_p,  g_qkv);
    cudaGetSymbolAddress((void**)&vt_p,   g_vt);
    cudaGetSymbolAddress((void**)&o_p,    g_o);
    cudaGetSymbolAddress((void**)&h_p,    g_h);
    cudaGetSymbolAddress((void**)&w_p,    g_w);

    __half* wq_p = w_p;
    __half* wp_p = w_p + 3 * 1024 * 1024;
    __half* w1_p = w_p + 4 * 1024 * 1024;
    __half* w2_p = w_p + 8 * 1024 * 1024;

    cudaFuncSetAttribute(gemm_h<1>,
        cudaFuncAttributeMaxDynamicSharedMemorySize, GM_SMEM);
    cudaFuncSetAttribute(gemm_h<2>,
        cudaFuncAttributeMaxDynamicSharedMemorySize, GM_SMEM);
    cudaFuncSetAttribute(gemm_h<3>,
        cudaFuncAttributeMaxDynamicSharedMemorySize, GM_SMEM);
    cudaFuncSetAttribute(flash_kernel,
        cudaFuncAttributeMaxDynamicSharedMemorySize, FA_SMEM);

    // 0) weights->fp16  +  adaLN mods, one co-running launch
    head_kernel<<<3072 + 48, 256>>>(
        (const float4*)w_qkv, (const float4*)w_proj,
        (const float4*)w_fc1, (const float4*)w_fc2, w_p,
        y, w_adaln, b_adaln, mods_p);

    // 1) xm = LN(x)*(1+sc_a)+sh_a -> fp16
    ln_mod_kernel<<<M_, 256>>>(x, mods_p, 0 * D_, 1 * D_, xm_p);

    // 2) qkv GEMM (Q*0.125, K -> g_qkv; V -> g_vt transposed)
    gemm_h<3><<<dim3(3 * D_ / 256, M_ / 128), 256, GM_SMEM>>>(
        xm_p, D_, wq_p, D_, qkv_p, 3 * D_, D_, nullptr, nullptr, nullptr, vt_p);

    // 3) fused attention -> o fp16
    flash_kernel<<<dim3(S_ / 256, B_ * H_), 512, FA_SMEM>>>(qkv_p, vt_p, o_p);

    // 4) x1 = x + g_a * (o @ w_proj^T + b_proj) -> d_out fp32
    gemm_h<2><<<dim3(D_ / 256, M_ / 128), 256, GM_SMEM>>>(
        o_p, D_, wp_p, D_, out, D_, D_, b_proj, x, mods_p + 2 * D_, nullptr);

    // 5) xm = LN(x1)*(1+sc_m)+sh_m -> fp16
    ln_mod_kernel<<<M_, 256>>>(out, mods_p, 3 * D_, 4 * D_, xm_p);

    // 6) h = gelu(xm @ w_fc1^T + b_fc1) -> fp16
    gemm_h<1><<<dim3(4 * D_ / 256, M_ / 128), 256, GM_SMEM>>>(
        xm_p, D_, w1_p, D_, h_p, 4 * D_, D_, b_fc1, nullptr, nullptr, nullptr);

    // 7) out = x1 + g_m * (h @ w_fc2^T + b_fc2) -> fp32
    gemm_h<2><<<dim3(D_ / 256, M_ / 128), 256, GM_SMEM>>>(
        h_p, 4 * D_, w2_p, 4 * D_, out, D_, 4 * D_, b_fc2, out, mods_p + 5 * D_, nullptr);
}

// round 16
// speedup vs baseline: 1.0424x; 1.0424x over previous
#include <cuda_runtime.h>
#include <cuda_fp16.h>
#include <cstdint>

// ----------------------------------------------------------------------------
// EBTBlock (DiT adaLN-Zero): B=8, S=1024, D=1024, H=16, DH=64, fp32.
// Round 16: base = R14 (929.8us; R15's head-merge reverted). Flash softmax in
// base-2 domain: 0.125*log2(e) folded into qkv's Q write, exp2f (bare EX2)
// replaces __expf, all scale FMULs deleted from the softmax chain.
// ----------------------------------------------------------------------------

#define B_    8
#define S_    1024
#define D_    1024
#define H_    16
#define DH_   64
#define M_    (B_ * S_)
#define SIXD_ (6 * D_)

// Scratch
__device__ float  g_mods[B_ * SIXD_];
__device__ __align__(16) __half g_xm[M_ * D_];
__device__ __align__(16) __half g_qkv[M_ * 3 * D_];
__device__ __align__(16) __half g_vt[B_ * H_ * DH_ * S_];
__device__ __align__(16) __half g_o[M_ * D_];
__device__ __align__(16) __half g_h[M_ * 4 * D_];
__device__ __align__(16) __half g_w[12 * 1024 * 1024];

// ===========================================================================
// helpers
// ===========================================================================
__device__ __forceinline__ uint32_t smem_u32(const void* p) {
    uint32_t a;
    asm("{ .reg .u64 t; cvta.to.shared.u64 t, %1; cvt.u32.u64 %0, t; }"
        : "=r"(a) : "l"(p));
    return a;
}
__device__ __forceinline__ void cpasync16(uint32_t dst, const void* src) {
    asm volatile("cp.async.ca.shared.global [%0], [%1], 16;"
                 :: "r"(dst), "l"(src) : "memory");
}
__device__ __forceinline__ void mma_f16(float* d, const uint32_t* a,
                                        const uint32_t* b) {
    asm volatile(
        "mma.sync.aligned.m16n8k16.row.col.f32.f16.f16.f32 "
        "{%0,%1,%2,%3}, {%4,%5,%6,%7}, {%8,%9}, {%0,%1,%2,%3};"
        : "+f"(d[0]), "+f"(d[1]), "+f"(d[2]), "+f"(d[3])
        : "r"(a[0]), "r"(a[1]), "r"(a[2]), "r"(a[3]), "r"(b[0]), "r"(b[1]));
}
__device__ __forceinline__ uint32_t packh2(float x, float y) {
    __half2 h = __floats2half2_rn(x, y);
    return *(uint32_t*)&h;
}
__device__ __forceinline__ float gelu_tanh(float x) {
    float x3 = x * x * x;
    float t = tanhf(0.7978845608028654f * (x + 0.044715f * x3));
    return 0.5f * x * (1.0f + t);
}

// 0.125 * log2(e): folded attention scale -> scores arrive in log2 domain
#define QSCALE 0.18033688011112042f

// ===========================================================================
// dense fp16 GEMM (NT): CTA 128x256, 8 warps (2x4), warp 64x64, k-chunk 64,
// 3-stage cp.async — at the mma.sync wall (R12/R14 core).
// EPI 0: half out  EPI 1: half gelu(v+bias)  EPI 2: fp32 resid+gate*(v+bias)
// EPI 3: qkv writer (Q scaled by QSCALE; K normal; V transposed)
// ===========================================================================
#define DSTRH 72
#define ASTGH (128 * DSTRH)
#define BSTGH (256 * DSTRH)
#define STGH  (ASTGH + BSTGH)
#define GM_SMEM (3 * STGH * 2)        // 165888 B

template <int EPI>
__global__ __launch_bounds__(256, 1)
void gemm_h(const __half* __restrict__ A, int lda,
            const __half* __restrict__ Bw, int ldb,
            void* __restrict__ Cv, int ldc,
            int K, const float* __restrict__ bias,
            const float* __restrict__ resid,
            const float* __restrict__ gate,
            __half* __restrict__ vt) {
    extern __shared__ __half smh[];
    const int tid = threadIdx.x, lane = tid & 31, wid = tid >> 5;
    const int wm = wid & 1, wn = wid >> 1;
    const int m0 = blockIdx.y * 128, n0 = blockIdx.x * 256;
    const uint32_t sbase = smem_u32(smh);
    const int q = lane & 3, lh = lane >> 2;

    float acc[4][8][4];
#pragma unroll
    for (int i = 0; i < 4; i++)
#pragma unroll
        for (int j = 0; j < 8; j++)
#pragma unroll
            for (int e = 0; e < 4; e++) acc[i][j][e] = 0.0f;

    const int nch = K >> 6;

    auto load_stage = [&](int s, int k0) {
#pragma unroll
        for (int it = 0; it < 4; it++) {
            int idx = tid + it * 256;
            int r = idx >> 3, c8 = (idx & 7) << 3;
            cpasync16(sbase + (uint32_t)(s * STGH + r * DSTRH + c8) * 2,
                      A + (size_t)(m0 + r) * lda + k0 + c8);
        }
#pragma unroll
        for (int it = 0; it < 8; it++) {
            int idx = tid + it * 256;
            int r = idx >> 3, c8 = (idx & 7) << 3;
            cpasync16(sbase + (uint32_t)(s * STGH + ASTGH + r * DSTRH + c8) * 2,
                      Bw + (size_t)(n0 + r) * ldb + k0 + c8);
        }
    };

    load_stage(0, 0);
    asm volatile("cp.async.commit_group;" ::: "memory");
    if (nch > 1) load_stage(1, 64);
    asm volatile("cp.async.commit_group;" ::: "memory");

    int stg = 0;
    for (int i = 0; i < nch; i++) {
        asm volatile("cp.async.wait_group 1;" ::: "memory");
        __syncthreads();
        if (i + 2 < nch) {
            int s2 = stg + 2; if (s2 >= 3) s2 -= 3;
            load_stage(s2, (i + 2) << 6);
        }
        asm volatile("cp.async.commit_group;" ::: "memory");

        const uint32_t* sAw = (const uint32_t*)(smh + stg * STGH);
        const uint32_t* sBw = sAw + ASTGH / 2;
#pragma unroll
        for (int kk = 0; kk < 4; kk++) {
            const int kw = kk * 8;
            uint32_t a[4][4];
#pragma unroll
            for (int ii = 0; ii < 4; ii++) {
                int rw = (wm * 64 + ii * 16 + lh) * (DSTRH / 2) + kw;
                a[ii][0] = sAw[rw + q];
                a[ii][1] = sAw[rw + 8 * (DSTRH / 2) + q];
                a[ii][2] = sAw[rw + q + 4];
                a[ii][3] = sAw[rw + 8 * (DSTRH / 2) + q + 4];
            }
#pragma unroll
            for (int j = 0; j < 8; j++) {
                int nw = (wn * 64 + j * 8 + lh) * (DSTRH / 2) + kw;
                uint32_t b[2];
                b[0] = sBw[nw + q];
                b[1] = sBw[nw + q + 4];
#pragma unroll
                for (int ii = 0; ii < 4; ii++)
                    mma_f16(acc[ii][j], a[ii], b);
            }
        }
        if (++stg == 3) stg = 0;
    }

#pragma unroll
    for (int ii = 0; ii < 4; ii++) {
        int gm0 = m0 + wm * 64 + ii * 16 + lh;
#pragma unroll
        for (int j = 0; j < 8; j++) {
            int gn = n0 + wn * 64 + j * 8 + 2 * q;
#pragma unroll
            for (int h = 0; h < 2; h++) {
                int gm = gm0 + h * 8;
                float v0 = acc[ii][j][h * 2], v1 = acc[ii][j][h * 2 + 1];
                if (EPI == 0) {
                    *(__half2*)((__half*)Cv + (size_t)gm * ldc + gn) =
                        __floats2half2_rn(v0, v1);
                } else if (EPI == 1) {
                    v0 = gelu_tanh(v0 + bias[gn]);
                    v1 = gelu_tanh(v1 + bias[gn + 1]);
                    *(__half2*)((__half*)Cv + (size_t)gm * ldc + gn) =
                        __floats2half2_rn(v0, v1);
                } else if (EPI == 2) {
                    float* C = (float*)Cv;
                    float2 o;
                    o.x = resid[(size_t)gm * ldc + gn] +
                          gate[(size_t)(gm >> 10) * SIXD_ + gn] * (v0 + bias[gn]);
                    o.y = resid[(size_t)gm * ldc + gn + 1] +
                          gate[(size_t)(gm >> 10) * SIXD_ + gn + 1] * (v1 + bias[gn + 1]);
                    *(float2*)(C + (size_t)gm * ldc + gn) = o;
                } else {            // EPI 3: qkv writer
                    if (gn < D_) {               // Q: fold 0.125*log2e
                        *(__half2*)((__half*)Cv + (size_t)gm * ldc + gn) =
                            __floats2half2_rn(v0 * QSCALE, v1 * QSCALE);
                    } else if (gn < 2 * D_) {    // K
                        *(__half2*)((__half*)Cv + (size_t)gm * ldc + gn) =
                            __floats2half2_rn(v0, v1);
                    } else {                     // V -> transposed
                        int hh = (gn - 2 * D_) >> 6, dh = (gn - 2 * D_) & 63;
                        int bb = gm >> 10, s = gm & 1023;
                        size_t rb = ((size_t)(bb * H_ + hh) * DH_ + dh) * S_ + s;
                        vt[rb]      = __float2half_rn(v0);
                        vt[rb + S_] = __float2half_rn(v1);
                    }
                }
            }
        }
    }
}

// ===========================================================================
// Fused flash attention, fp16 mma, q-tile 256, K/V double-buffered,
// P in registers (C-frag == A-frag identity). Scores in log2 domain ->
// softmax via exp2f (bare MUFU.EX2, no FMULs).
// grid (S/256, B*H), 512 thr. SMEM = 108544 B.
// ===========================================================================
#define QSH 72
#define VTH 136
#define KSTG (128 * QSH)
#define VSTG (64 * VTH)
#define FA_SMEM ((256 * QSH + 2 * KSTG + 2 * VSTG) * 2)

__global__ __launch_bounds__(512, 1)
void flash_kernel(const __half* __restrict__ qkv,
                  const __half* __restrict__ vt,
                  __half* __restrict__ O) {
    extern __shared__ __half fsh[];
    __half* Qs = fsh;
    __half* Ks = Qs + 256 * QSH;
    __half* Vs = Ks + 2 * KSTG;
    const uint32_t sbQ = smem_u32(Qs), sbK = smem_u32(Ks), sbV = smem_u32(Vs);
    const uint32_t* Qw = (const uint32_t*)Qs;

    const int tid = threadIdx.x, lane = tid & 31, wid = tid >> 5;
    const int q = lane & 3, lh = lane >> 2;
    const int w16 = wid * 16;
    const int bh = blockIdx.y, bb = bh >> 4, hh = bh & 15;
    const int q0 = blockIdx.x * 256;
    const size_t base = (size_t)bb * S_ * 3 * D_ + (size_t)hh * DH_;
    const size_t vbase = (size_t)bh * DH_ * S_;

    auto load_kv = [&](int s, int kv0) {
        const uint32_t kb = sbK + (uint32_t)(s * KSTG) * 2;
        const uint32_t vb = sbV + (uint32_t)(s * VSTG) * 2;
#pragma unroll
        for (int it = 0; it < 2; it++) {
            int idx = tid + it * 512;
            int r = idx >> 3, c8 = (idx & 7) << 3;
            cpasync16(kb + (uint32_t)(r * QSH + c8) * 2,
                      qkv + base + D_ + (size_t)(kv0 + r) * 3 * D_ + c8);
        }
#pragma unroll
        for (int it = 0; it < 2; it++) {
            int idx = tid + it * 512;
            int r = idx >> 4, c8 = (idx & 15) << 3;
            cpasync16(vb + (uint32_t)(r * VTH + c8) * 2,
                      vt + vbase + (size_t)r * S_ + kv0 + c8);
        }
    };

#pragma unroll
    for (int it = 0; it < 4; it++) {
        int idx = tid + it * 512;
        int r = idx >> 3, c8 = (idx & 7) << 3;
        cpasync16(sbQ + (uint32_t)(r * QSH + c8) * 2,
                  qkv + base + (size_t)(q0 + r) * 3 * D_ + c8);
    }
    load_kv(0, 0);
    asm volatile("cp.async.commit_group;" ::: "memory");

    float accO[8][4];
#pragma unroll
    for (int j = 0; j < 8; j++)
#pragma unroll
        for (int e = 0; e < 4; e++) accO[j][e] = 0.0f;
    float mstate[2] = {-1e30f, -1e30f};
    float lstate[2] = {0.0f, 0.0f};

    for (int t = 0; t < 8; t++) {
        if (t + 1 < 8) {
            load_kv((t + 1) & 1, (t + 1) * 128);
            asm volatile("cp.async.commit_group;" ::: "memory");
            asm volatile("cp.async.wait_group 1;" ::: "memory");
        } else {
            asm volatile("cp.async.wait_group 0;" ::: "memory");
        }
        __syncthreads();

        const uint32_t* Kw = (const uint32_t*)(Ks + (t & 1) * KSTG);
        const uint32_t* Vw = (const uint32_t*)(Vs + (t & 1) * VSTG);

        // S2 = Qscaled @ K^T  (log2-domain scores)
        float sc[16][4];
#pragma unroll
        for (int j = 0; j < 16; j++)
#pragma unroll
            for (int e = 0; e < 4; e++) sc[j][e] = 0.0f;
#pragma unroll
        for (int kk = 0; kk < 4; kk++) {
            const int kw = kk * 8;
            uint32_t a[4];
            int rw = (w16 + lh) * (QSH / 2) + kw;
            a[0] = Qw[rw + q];
            a[1] = Qw[rw + 8 * (QSH / 2) + q];
            a[2] = Qw[rw + q + 4];
            a[3] = Qw[rw + 8 * (QSH / 2) + q + 4];
#pragma unroll
            for (int j = 0; j < 16; j++) {
                int nw = (j * 8 + lh) * (QSH / 2) + kw;
                uint32_t b[2] = {Kw[nw + q], Kw[nw + q + 4]};
                mma_f16(sc[j], a, b);
            }
        }

        // online softmax per row pair, base-2 (exp2f = bare EX2)
#pragma unroll
        for (int h2 = 0; h2 < 2; h2++) {
            float mx = -1e30f;
#pragma unroll
            for (int j = 0; j < 16; j++)
                mx = fmaxf(mx, fmaxf(sc[j][h2 * 2], sc[j][h2 * 2 + 1]));
            mx = fmaxf(mx, __shfl_xor_sync(0xffffffffu, mx, 1));
            mx = fmaxf(mx, __shfl_xor_sync(0xffffffffu, mx, 2));
            float mn = fmaxf(mstate[h2], mx);
            float f = exp2f(mstate[h2] - mn);
            mstate[h2] = mn;
            float rs = 0.0f;
#pragma unroll
            for (int j = 0; j < 16; j++) {
#pragma unroll
                for (int e = 0; e < 2; e++) {
                    float p = exp2f(sc[j][h2 * 2 + e] - mn);
                    rs += p;
                    sc[j][h2 * 2 + e] = p;
                }
            }
            rs += __shfl_xor_sync(0xffffffffu, rs, 1);
            rs += __shfl_xor_sync(0xffffffffu, rs, 2);
            lstate[h2] = lstate[h2] * f + rs;
#pragma unroll
            for (int j = 0; j < 8; j++) {
                accO[j][h2 * 2] *= f;
                accO[j][h2 * 2 + 1] *= f;
            }
        }

        // O += P @ V — P direct from C-fragments (layout identity)
#pragma unroll
        for (int kb = 0; kb < 8; kb++) {
            uint32_t a[4];
            a[0] = packh2(sc[2 * kb][0],     sc[2 * kb][1]);
            a[1] = packh2(sc[2 * kb][2],     sc[2 * kb][3]);
            a[2] = packh2(sc[2 * kb + 1][0], sc[2 * kb + 1][1]);
            a[3] = packh2(sc[2 * kb + 1][2], sc[2 * kb + 1][3]);
            const int kw = kb * 8;
#pragma unroll
            for (int j = 0; j < 8; j++) {
                int nw = (j * 8 + lh) * (VTH / 2) + kw;
                uint32_t b[2] = {Vw[nw + q], Vw[nw + q + 4]};
                mma_f16(accO[j], a, b);
            }
        }
        __syncthreads();
    }

    float inv0 = 1.0f / lstate[0], inv1 = 1.0f / lstate[1];
#pragma unroll
    for (int h2 = 0; h2 < 2; h2++) {
        float inv = h2 ? inv1 : inv0;
        size_t row = (size_t)(bb * S_ + q0 + w16 + lh + 8 * h2);
#pragma unroll
        for (int j = 0; j < 8; j++) {
            *(__half2*)(O + row * D_ + hh * DH_ + j * 8 + 2 * q) =
                __floats2half2_rn(accO[j][h2 * 2] * inv,
                                  accO[j][h2 * 2 + 1] * inv);
        }
    }
}

// ===========================================================================
// small kernels (R14 versions)
// ===========================================================================
__device__ __forceinline__ float blk_reduce_sum(float v, float* red) {
    int lane = threadIdx.x & 31, w = threadIdx.x >> 5;
#pragma unroll
    for (int o = 16; o; o >>= 1) v += __shfl_xor_sync(0xffffffffu, v, o);
    if (lane == 0) red[w] = v;
    __syncthreads();
    if (w == 0) {
        v = (lane < 8) ? red[lane] : 0.0f;
#pragma unroll
        for (int o = 4; o; o >>= 1) v += __shfl_xor_sync(0xffffffffu, v, o);
        if (lane == 0) red[0] = v;
    }
    __syncthreads();
    float r = red[0];
    __syncthreads();
    return r;
}

__global__ void convw_kernel(const float4* __restrict__ s0,
                             const float4* __restrict__ s1,
                             const float4* __restrict__ s2,
                             const float4* __restrict__ s3,
                             __half* __restrict__ dst) {
    int base = blockIdx.x * 1024 + threadIdx.x;
#pragma unroll
    for (int k = 0; k < 4; k++) {
        int i = base + k * 256;
        const float4* s;
        int off;
        if (i < 786432)        { s = s0; off = i; }
        else if (i < 1048576)  { s = s1; off = i - 786432; }
        else if (i < 2097152)  { s = s2; off = i - 1048576; }
        else                   { s = s3; off = i - 2097152; }
        float4 v = s[off];
        __half2 h0 = __floats2half2_rn(v.x, v.y);
        __half2 h1 = __floats2half2_rn(v.z, v.w);
        *(uint2*)(dst + 4 * (size_t)i) = make_uint2(
            *(uint32_t*)&h0, *(uint32_t*)&h1);
    }
}

__global__ void mods_kernel(const float* __restrict__ y,
                            const float* __restrict__ w,
                            const float* __restrict__ bias,
                            float* __restrict__ mods) {
    __shared__ float sy[4][D_];
    int tid = threadIdx.x;
    int g = blockIdx.y;
#pragma unroll
    for (int b4 = 0; b4 < 4; b4++) {
        float4 yv = ((const float4*)(y + (4 * g + b4) * D_))[tid];
        sy[b4][tid * 4 + 0] = yv.x / (1.0f + expf(-yv.x));
        sy[b4][tid * 4 + 1] = yv.y / (1.0f + expf(-yv.y));
        sy[b4][tid * 4 + 2] = yv.z / (1.0f + expf(-yv.z));
        sy[b4][tid * 4 + 3] = yv.w / (1.0f + expf(-yv.w));
    }
    __syncthreads();
    int j = blockIdx.x * 256 + tid;
    float acc[4];
#pragma unroll
    for (int b4 = 0; b4 < 4; b4++) acc[b4] = bias[j];
    const float4* w4 = (const float4*)(w + (long)j * D_);
#pragma unroll 4
    for (int k = 0; k < D_ / 4; k++) {
        float4 wv = w4[k];
#pragma unroll
        for (int b4 = 0; b4 < 4; b4++) {
            acc[b4] += sy[b4][4 * k + 0] * wv.x + sy[b4][4 * k + 1] * wv.y +
                       sy[b4][4 * k + 2] * wv.z + sy[b4][4 * k + 3] * wv.w;
        }
    }
#pragma unroll
    for (int b4 = 0; b4 < 4; b4++)
        mods[(4 * g + b4) * SIXD_ + j] = acc[b4];
}

__global__ void ln_mod_kernel(const float* __restrict__ X,
                              const float* __restrict__ mods,
                              int sh_off, int sc_off,
                              __half* __restrict__ out) {
    __shared__ float red[32];
    long row = blockIdx.x;
    int b = (int)(row >> 10);
    int tid = threadIdx.x;
    float4 v = ((const float4*)(X + row * D_))[tid];
    float s = v.x + v.y + v.z + v.w;
    s = blk_reduce_sum(s, red);
    float mean = s * (1.0f / D_);
    float dx = v.x - mean, dy = v.y - mean, dz = v.z - mean, dw = v.w - mean;
    float sq = dx * dx + dy * dy + dz * dz + dw * dw;
    sq = blk_reduce_sum(sq, red);
    float inv = rsqrtf(sq * (1.0f / D_) + 1e-5f);
    const float* mrow = mods + b * SIXD_;
    int c = tid * 4;
    float o0 = dx * inv * (1.0f + mrow[sc_off + c + 0]) + mrow[sh_off + c + 0];
    float o1 = dy * inv * (1.0f + mrow[sc_off + c + 1]) + mrow[sh_off + c + 1];
    float o2 = dz * inv * (1.0f + mrow[sc_off + c + 2]) + mrow[sh_off + c + 2];
    float o3 = dw * inv * (1.0f + mrow[sc_off + c + 3]) + mrow[sh_off + c + 3];
    __half2 h0 = __floats2half2_rn(o0, o1);
    __half2 h1 = __floats2half2_rn(o2, o3);
    *(uint2*)(out + row * (size_t)D_ + c) = make_uint2(
        *(uint32_t*)&h0, *(uint32_t*)&h1);
}

// ===========================================================================
// host launcher
// ===========================================================================
extern "C" void kernel_launch(void* const* d_in, const int* in_sizes, int n_in,
                              void* d_out, int out_size) {
    const float* x       = (const float*)d_in[0];
    const float* y       = (const float*)d_in[1];
    const float* w_adaln = (const float*)d_in[2];
    const float* b_adaln = (const float*)d_in[3];
    const float* w_qkv   = (const float*)d_in[4];
    const float* w_proj  = (const float*)d_in[5];
    const float* b_proj  = (const float*)d_in[6];
    const float* w_fc1   = (const float*)d_in[7];
    const float* b_fc1   = (const float*)d_in[8];
    const float* w_fc2   = (const float*)d_in[9];
    const float* b_fc2   = (const float*)d_in[10];
    float* out = (float*)d_out;

    float *mods_p;
    __half *xm_p, *qkv_p, *vt_p, *o_p, *h_p, *w_p;
    cudaGetSymbolAddress((void**)&mods_p, g_mods);
    cudaGetSymbolAddress((void**)&xm_p,   g_xm);
    cudaGetSymbolAddress((void**)&qkv_p,  g_qkv);
    cudaGetSymbolAddress((void**)&vt_p,   g_vt);
    cudaGetSymbolAddress((void**)&o_p,    g_o);
    cudaGetSymbolAddress((void**)&h_p,    g_h);
    cudaGetSymbolAddress((void**)&w_p,    g_w);

    __half* wq_p = w_p;
    __half* wp_p = w_p + 3 * 1024 * 1024;
    __half* w1_p = w_p + 4 * 1024 * 1024;
    __half* w2_p = w_p + 8 * 1024 * 1024;

    cudaFuncSetAttribute(gemm_h<1>,
        cudaFuncAttributeMaxDynamicSharedMemorySize, GM_SMEM);
    cudaFuncSetAttribute(gemm_h<2>,
        cudaFuncAttributeMaxDynamicSharedMemorySize, GM_SMEM);
    cudaFuncSetAttribute(gemm_h<3>,
        cudaFuncAttributeMaxDynamicSharedMemorySize, GM_SMEM);
    cudaFuncSetAttribute(flash_kernel,
        cudaFuncAttributeMaxDynamicSharedMemorySize, FA_SMEM);

    // 0) convert weights to fp16
    convw_kernel<<<3072, 256>>>((const float4*)w_qkv, (const float4*)w_proj,
                                (const float4*)w_fc1, (const float4*)w_fc2,
                                w_p);

    // 1) adaLN mods
    mods_kernel<<<dim3(SIXD_ / 256, 2), 256>>>(y, w_adaln, b_adaln, mods_p);

    // 2) xm = LN(x)*(1+sc_a)+sh_a -> fp16
    ln_mod_kernel<<<M_, 256>>>(x, mods_p, 0 * D_, 1 * D_, xm_p);

    // 3) qkv GEMM (Q*QSCALE, K -> g_qkv; V -> g_vt transposed)
    gemm_h<3><<<dim3(3 * D_ / 256, M_ / 128), 256, GM_SMEM>>>(
        xm_p, D_, wq_p, D_, qkv_p, 3 * D_, D_, nullptr, nullptr, nullptr, vt_p);

    // 4) fused attention -> o fp16
    flash_kernel<<<dim3(S_ / 256, B_ * H_), 512, FA_SMEM>>>(qkv_p, vt_p, o_p);

    // 5) x1 = x + g_a * (o @ w_proj^T + b_proj) -> d_out fp32
    gemm_h<2><<<dim3(D_ / 256, M_ / 128), 256, GM_SMEM>>>(
        o_p, D_, wp_p, D_, out, D_, D_, b_proj, x, mods_p + 2 * D_, nullptr);

    // 6) xm = LN(x1)*(1+sc_m)+sh_m -> fp16
    ln_mod_kernel<<<M_, 256>>>(out, mods_p, 3 * D_, 4 * D_, xm_p);

    // 7) h = gelu(xm @ w_fc1^T + b_fc1) -> fp16
    gemm_h<1><<<dim3(4 * D_ / 256, M_ / 128), 256, GM_SMEM>>>(
        xm_p, D_, w1_p, D_, h_p, 4 * D_, D_, b_fc1, nullptr, nullptr, nullptr);

    // 8) out = x1 + g_m * (h @ w_fc2^T + b_fc2) -> fp32
    gemm_h<2><<<dim3(D_ / 256, M_ / 128), 256, GM_SMEM>>>(
        h_p, 4 * D_, w2_p, 4 * D_, out, D_, 4 * D_, b_fc2, out, mods_p + 5 * D_, nullptr);
}